// round 4
// baseline (speedup 1.0000x reference)
#include <cuda_runtime.h>
#include <stdint.h>

#define N_NODES   100000
#define N_EDGES   1200000
#define N_GRAPHS  128
#define D         64
#define N_CLASSES 10

// Scratch (device globals: allocation-free). 16B alignment for float4 / red.v4.
__device__ __align__(128) float g_h[N_NODES * D];     // GEMM output of current layer
__device__ __align__(128) float g_agg[N_NODES * D];   // aggregation buffer / next-layer input
__device__ __align__(128) float g_dinv[N_NODES];      // deg accumulator, then rsqrt(deg)
__device__ __align__(128) float g_pool[N_GRAPHS * D]; // pooled sums
__device__ int g_cnt[N_GRAPHS];
__device__ int g_idx64;                               // 1 if indices are int64, 0 if int32

__device__ __forceinline__ void red_add_v4(float* addr, float4 v) {
    asm volatile("red.global.add.v4.f32 [%0], {%1, %2, %3, %4};"
                 :: "l"(addr), "f"(v.x), "f"(v.y), "f"(v.z), "f"(v.w)
                 : "memory");
}

// ---------------------------------------------------------------------------
// Detect int32 vs int64 edge indices: if int64 (values < 2^31), every high
// 32-bit word is zero. If int32, the "odd" words are edge endpoints (random in
// [0,1e5)) — OR over 2048 of them is nonzero with overwhelming probability.
// ---------------------------------------------------------------------------
__global__ void detect_kernel(const int* ei_words) {
    int v = 0;
    for (int i = threadIdx.x; i < 2048; i += blockDim.x) v |= ei_words[2 * i + 1];
    int nonzero = __syncthreads_or(v != 0);
    if (threadIdx.x == 0) g_idx64 = nonzero ? 0 : 1;
}

__device__ __forceinline__ int load_idx(const void* p, long long i) {
    return g_idx64 ? (int)((const long long*)p)[i] : ((const int*)p)[i];
}

// Degree: deg[i] = #(col == i); self-loop (+1) folded into dinv transform.
__global__ void deg_kernel(const void* ei) {
    int e = blockIdx.x * blockDim.x + threadIdx.x;
    if (e >= N_EDGES) return;
    int c = load_idx(ei, (long long)N_EDGES + e);
    atomicAdd(&g_dinv[c], 1.0f);
}

__global__ void dinv_kernel() {
    int i = blockIdx.x * blockDim.x + threadIdx.x;
    if (i < N_NODES) g_dinv[i] = rsqrtf(g_dinv[i] + 1.0f);
}

// ---------------------------------------------------------------------------
// GEMM: g_h = (relu_in ? relu(A) : A) @ W, A:[N,64] row-major, W:[64,64].
// Block = 256 threads, 64 rows per block. W + A tiles in smem.
// Thread (grp = t>>4, q = t&15) computes rows grp*4..+3, cols q*4..+3.
// ---------------------------------------------------------------------------
__global__ __launch_bounds__(256) void gemm_kernel(const float* __restrict__ A,
                                                   const float* __restrict__ W,
                                                   int relu_in) {
    __shared__ float sA[64 * 64];
    __shared__ float sW[64 * 64];
    const int t = threadIdx.x;
    const int base = blockIdx.x * 64;

    for (int i = t; i < 1024; i += 256)
        ((float4*)sW)[i] = ((const float4*)W)[i];

    for (int i = t; i < 1024; i += 256) {
        int row = i >> 4;          // 0..63
        int quad = i & 15;         // 0..15
        int gr = base + row;
        float4 v = make_float4(0.f, 0.f, 0.f, 0.f);
        if (gr < N_NODES) v = ((const float4*)A)[gr * 16 + quad];
        if (relu_in) {
            v.x = fmaxf(v.x, 0.f); v.y = fmaxf(v.y, 0.f);
            v.z = fmaxf(v.z, 0.f); v.w = fmaxf(v.w, 0.f);
        }
        ((float4*)sA)[i] = v;
    }
    __syncthreads();

    const int q   = t & 15;
    const int grp = t >> 4;
    float4 acc0 = make_float4(0.f,0.f,0.f,0.f);
    float4 acc1 = make_float4(0.f,0.f,0.f,0.f);
    float4 acc2 = make_float4(0.f,0.f,0.f,0.f);
    float4 acc3 = make_float4(0.f,0.f,0.f,0.f);

    #pragma unroll
    for (int k = 0; k < 64; k++) {
        float4 w = ((const float4*)(sW + k * 64))[q];
        float a0 = sA[(grp * 4 + 0) * 64 + k];
        float a1 = sA[(grp * 4 + 1) * 64 + k];
        float a2 = sA[(grp * 4 + 2) * 64 + k];
        float a3 = sA[(grp * 4 + 3) * 64 + k];
        acc0.x += a0 * w.x; acc0.y += a0 * w.y; acc0.z += a0 * w.z; acc0.w += a0 * w.w;
        acc1.x += a1 * w.x; acc1.y += a1 * w.y; acc1.z += a1 * w.z; acc1.w += a1 * w.w;
        acc2.x += a2 * w.x; acc2.y += a2 * w.y; acc2.z += a2 * w.z; acc2.w += a2 * w.w;
        acc3.x += a3 * w.x; acc3.y += a3 * w.y; acc3.z += a3 * w.z; acc3.w += a3 * w.w;
    }

    float4 accs[4] = {acc0, acc1, acc2, acc3};
    #pragma unroll
    for (int j = 0; j < 4; j++) {
        int gr = base + grp * 4 + j;
        if (gr < N_NODES) ((float4*)g_h)[gr * 16 + q] = accs[j];
    }
}

// agg[i] = h[i] * dinv[i]^2 (self-loop) + bias  — replaces zero-init.
__global__ void init_kernel(const float* __restrict__ bias) {
    int id = blockIdx.x * blockDim.x + threadIdx.x;
    if (id >= N_NODES * 16) return;
    int node = id >> 4, q = id & 15;
    float di = g_dinv[node];
    float s  = di * di;
    float4 v = ((const float4*)g_h)[id];
    float4 b = ((const float4*)bias)[q];
    float4 o = make_float4(v.x * s + b.x, v.y * s + b.y, v.z * s + b.z, v.w * s + b.w);
    ((float4*)g_agg)[id] = o;
}

// Edge scatter: 16 threads per edge, each one float4 slice.
__global__ void scatter_kernel(const void* __restrict__ ei) {
    long long tid = (long long)blockIdx.x * blockDim.x + threadIdx.x;
    if (tid >= (long long)N_EDGES * 16) return;
    int e = (int)(tid >> 4);
    int q = (int)(tid & 15);
    int r = load_idx(ei, e);
    int c = load_idx(ei, (long long)N_EDGES + e);
    float norm = g_dinv[r] * g_dinv[c];
    float4 v = ((const float4*)g_h)[r * 16 + q];
    v.x *= norm; v.y *= norm; v.z *= norm; v.w *= norm;
    red_add_v4(&g_agg[c * D + q * 4], v);
}

// Graph sizes via binary search on the sorted batch vector (no atomics).
__global__ void cnt_kernel(const void* __restrict__ batch) {
    int b = threadIdx.x;
    if (b >= N_GRAPHS) return;
    int lo = 0, hi = N_NODES;
    while (lo < hi) { int m = (lo + hi) >> 1; if (load_idx(batch, m) < b) lo = m + 1; else hi = m; }
    int lo2 = lo, hi2 = N_NODES;
    while (lo2 < hi2) { int m = (lo2 + hi2) >> 1; if (load_idx(batch, m) < b + 1) lo2 = m + 1; else hi2 = m; }
    g_cnt[b] = hi2 - lo;
}

__global__ void pool_kernel(const void* __restrict__ batch) {
    int id = blockIdx.x * blockDim.x + threadIdx.x;
    if (id >= N_NODES * 16) return;
    int node = id >> 4, q = id & 15;
    int b = load_idx(batch, node);
    float4 v = ((const float4*)g_agg)[id];
    red_add_v4(&g_pool[b * D + q * 4], v);
}

__global__ void final_kernel(const float* __restrict__ linW,
                             const float* __restrict__ linb,
                             float* __restrict__ out) {
    int id = blockIdx.x * blockDim.x + threadIdx.x;
    if (id >= N_GRAPHS * N_CLASSES) return;
    int b = id / N_CLASSES, c = id % N_CLASSES;
    float inv = 1.0f / fmaxf((float)g_cnt[b], 1.0f);
    float acc = linb[c];
    #pragma unroll
    for (int d = 0; d < D; d++)
        acc += (g_pool[b * D + d] * inv) * linW[d * N_CLASSES + c];
    out[id] = acc;
}

extern "C" void kernel_launch(void* const* d_in, const int* in_sizes, int n_in,
                              void* d_out, int out_size) {
    const float* x    = (const float*)d_in[0];
    const void*  ei   = d_in[1];
    const void*  bat  = d_in[2];
    const float* W1   = (const float*)d_in[3];
    const float* b1   = (const float*)d_in[4];
    const float* W2   = (const float*)d_in[5];
    const float* b2   = (const float*)d_in[6];
    const float* W3   = (const float*)d_in[7];
    const float* b3   = (const float*)d_in[8];
    const float* linW = (const float*)d_in[9];
    const float* linb = (const float*)d_in[10];
    float* out = (float*)d_out;

    void *dinv_p, *pool_p, *agg_p;
    cudaGetSymbolAddress(&dinv_p, g_dinv);
    cudaGetSymbolAddress(&pool_p, g_pool);
    cudaGetSymbolAddress(&agg_p,  g_agg);
    const float* agg = (const float*)agg_p;

    cudaMemsetAsync(dinv_p, 0, N_NODES * sizeof(float));
    cudaMemsetAsync(pool_p, 0, N_GRAPHS * D * sizeof(float));

    detect_kernel<<<1, 256>>>((const int*)ei);
    deg_kernel<<<(N_EDGES + 255) / 256, 256>>>(ei);
    dinv_kernel<<<(N_NODES + 255) / 256, 256>>>();
    cnt_kernel<<<1, 128>>>(bat);

    const int GEMM_BLOCKS = (N_NODES + 63) / 64;
    const int NODE16      = (N_NODES * 16 + 255) / 256;
    const int EDGE16      = (int)(((long long)N_EDGES * 16 + 255) / 256);

    // Layer 1
    gemm_kernel<<<GEMM_BLOCKS, 256>>>(x, W1, 0);
    init_kernel<<<NODE16, 256>>>(b1);
    scatter_kernel<<<EDGE16, 256>>>(ei);
    // Layer 2 (relu fused into GEMM input load)
    gemm_kernel<<<GEMM_BLOCKS, 256>>>(agg, W2, 1);
    init_kernel<<<NODE16, 256>>>(b2);
    scatter_kernel<<<EDGE16, 256>>>(ei);
    // Layer 3
    gemm_kernel<<<GEMM_BLOCKS, 256>>>(agg, W3, 1);
    init_kernel<<<NODE16, 256>>>(b3);
    scatter_kernel<<<EDGE16, 256>>>(ei);

    // Pool + classifier
    pool_kernel<<<NODE16, 256>>>(bat);
    final_kernel<<<(N_GRAPHS * N_CLASSES + 255) / 256, 256>>>(linW, linb, out);
}

// round 5
// speedup vs baseline: 1.2397x; 1.2397x over previous
#include <cuda_runtime.h>
#include <stdint.h>

#define N_NODES   100000
#define N_EDGES   1200000
#define N_GRAPHS  128
#define D         64
#define N_CLASSES 10

#define SCAN_NB   ((N_NODES + 1023) / 1024)   // 98 blocks of 1024 items

// ---- device scratch (allocation-free) ----
__device__ __align__(128) float g_h[N_NODES * D];      // GEMM output (pre-aggregation)
__device__ __align__(128) float g_agg[N_NODES * D];    // aggregated features / next input
__device__ __align__(128) float g_dinv[N_NODES];       // rsqrt(deg+1)
__device__ __align__(128) int   g_deg[N_NODES];        // in-degree histogram
__device__ __align__(128) int   g_off[N_NODES + 1];    // CSR row offsets (by target col)
__device__ __align__(128) int   g_cursor[N_NODES];     // fill cursors
__device__ __align__(128) float2 g_edge[N_EDGES];      // CSR payload: {src_as_bits, norm}
__device__ __align__(128) int   g_bsum[SCAN_NB];       // scan block sums
__device__ __align__(128) float g_pool[N_GRAPHS * D];
__device__ int g_lb[N_GRAPHS + 1];                     // graph boundary lower-bounds
__device__ int g_ei64;                                 // edge_index is int64?
__device__ int g_bat64;                                // batch is int64?

// ---------------------------------------------------------------------------
// f32x2 helpers (sm_103a packed dual-FMA; ptxas never emits FFMA2 from C++)
// ---------------------------------------------------------------------------
__device__ __forceinline__ void fma2(unsigned long long& d,
                                     unsigned long long a,
                                     unsigned long long b) {
    asm("fma.rn.f32x2 %0, %1, %2, %0;" : "+l"(d) : "l"(a), "l"(b));
}
__device__ __forceinline__ unsigned long long dupf(float a) {
    unsigned long long u;
    asm("mov.b64 %0, {%1, %1};" : "=l"(u) : "f"(a));
    return u;
}
__device__ __forceinline__ float2 unpack2(unsigned long long u) {
    float2 f;
    asm("mov.b64 {%0, %1}, %2;" : "=f"(f.x), "=f"(f.y) : "l"(u));
    return f;
}
__device__ __forceinline__ void red_add_v4(float* addr, float4 v) {
    asm volatile("red.global.add.v4.f32 [%0], {%1, %2, %3, %4};"
                 :: "l"(addr), "f"(v.x), "f"(v.y), "f"(v.z), "f"(v.w)
                 : "memory");
}

// ---------------------------------------------------------------------------
// dtype detection: int64 arrays have zero high words; int32 arrays show data.
// ---------------------------------------------------------------------------
__global__ void detect_kernel(const int* ei_words, const int* bat_words) {
    int v = 0;
    // edge index: odd words 1..4095 — int32 case these are random node ids
    for (int i = threadIdx.x; i < 2048; i += blockDim.x) v |= ei_words[2 * i + 1];
    int ei_nz = __syncthreads_or(v != 0);
    // batch: odd words near end of the first N_NODES words (safe for both layouts).
    // int32: these are batch values near index 1e5 (~127, nonzero). int64: high halves = 0.
    int w = 0;
    for (int i = threadIdx.x; i < 2048; i += blockDim.x) {
        int wi = N_NODES - 1 - 2 * i;      // odd/even mix; take odd only
        wi -= (1 - (wi & 1));              // make odd
        if (wi >= 1) w |= bat_words[wi];
    }
    int bat_nz = __syncthreads_or(w != 0);
    if (threadIdx.x == 0) { g_ei64 = ei_nz ? 0 : 1; g_bat64 = bat_nz ? 0 : 1; }
}

__device__ __forceinline__ int load_ei(const void* p, long long i) {
    return g_ei64 ? (int)((const long long*)p)[i] : ((const int*)p)[i];
}
__device__ __forceinline__ int load_bat(const void* p, int i) {
    return g_bat64 ? (int)((const long long*)p)[i] : ((const int*)p)[i];
}

// ---------------------------------------------------------------------------
// degree histogram + dinv
// ---------------------------------------------------------------------------
__global__ void deg_kernel(const void* ei) {
    int e = blockIdx.x * blockDim.x + threadIdx.x;
    if (e >= N_EDGES) return;
    atomicAdd(&g_deg[load_ei(ei, (long long)N_EDGES + e)], 1);
}
__global__ void dinv_kernel() {
    int i = blockIdx.x * blockDim.x + threadIdx.x;
    if (i < N_NODES) g_dinv[i] = rsqrtf((float)g_deg[i] + 1.0f);
}

// ---------------------------------------------------------------------------
// 3-kernel exclusive scan of g_deg -> g_off / g_cursor
// ---------------------------------------------------------------------------
__global__ void scan1_kernel() {
    __shared__ int s[256];
    int t = threadIdx.x;
    int base = blockIdx.x * 1024 + t * 4;
    int sum = 0;
    #pragma unroll
    for (int j = 0; j < 4; j++) { int i = base + j; if (i < N_NODES) sum += g_deg[i]; }
    s[t] = sum; __syncthreads();
    for (int o = 128; o > 0; o >>= 1) { if (t < o) s[t] += s[t + o]; __syncthreads(); }
    if (t == 0) g_bsum[blockIdx.x] = s[0];
}
__global__ void scan2_kernel() {
    __shared__ int s[128];
    int t = threadIdx.x;
    s[t] = (t < SCAN_NB) ? g_bsum[t] : 0;
    __syncthreads();
    for (int o = 1; o < 128; o <<= 1) {
        int v = (t >= o) ? s[t - o] : 0;
        __syncthreads(); s[t] += v; __syncthreads();
    }
    if (t < SCAN_NB) g_bsum[t] = (t == 0) ? 0 : s[t - 1];
}
__global__ void scan3_kernel() {
    __shared__ int ts[256];
    int t = threadIdx.x;
    int base = blockIdx.x * 1024 + t * 4;
    int v[4];
    #pragma unroll
    for (int j = 0; j < 4; j++) v[j] = (base + j < N_NODES) ? g_deg[base + j] : 0;
    int lsum = v[0] + v[1] + v[2] + v[3];
    ts[t] = lsum; __syncthreads();
    for (int o = 1; o < 256; o <<= 1) {
        int x = (t >= o) ? ts[t - o] : 0;
        __syncthreads(); ts[t] += x; __syncthreads();
    }
    int pre = g_bsum[blockIdx.x] + ((t == 0) ? 0 : ts[t - 1]);
    #pragma unroll
    for (int j = 0; j < 4; j++) {
        int i = base + j;
        if (i < N_NODES) { g_off[i] = pre; g_cursor[i] = pre; }
        pre += v[j];
    }
    if (blockIdx.x == 0 && t == 0) g_off[N_NODES] = N_EDGES;
}

// CSR fill: payload = {src row bits, norm = dinv[r]*dinv[c]}
__global__ void fill_kernel(const void* __restrict__ ei) {
    int e = blockIdx.x * blockDim.x + threadIdx.x;
    if (e >= N_EDGES) return;
    int r = load_ei(ei, e);
    int c = load_ei(ei, (long long)N_EDGES + e);
    int pos = atomicAdd(&g_cursor[c], 1);
    g_edge[pos] = make_float2(__int_as_float(r), g_dinv[r] * g_dinv[c]);
}

// ---------------------------------------------------------------------------
// GEMM: g_h = (relu? relu(A):A) @ W.  64-row tiles, 128 threads/block.
// Thread (grp=t>>3, q2=t&7): rows grp*4..+3, cols q2*8..+7, f32x2 accumulators.
// ---------------------------------------------------------------------------
#define SA_STRIDE 66   // conflict-free scalar broadcast reads
__global__ __launch_bounds__(128) void gemm_kernel(const float* __restrict__ A,
                                                   const float* __restrict__ W,
                                                   int relu_in) {
    __shared__ float sA[64 * SA_STRIDE];
    __shared__ float sW[64 * 64];
    const int t = threadIdx.x;
    const int base = blockIdx.x * 64;

    for (int i = t; i < 1024; i += 128)
        ((float4*)sW)[i] = ((const float4*)W)[i];

    for (int i = t; i < 1024; i += 128) {
        int row = i >> 4, quad = i & 15;
        int gr = base + row;
        float4 v = make_float4(0.f, 0.f, 0.f, 0.f);
        if (gr < N_NODES) v = ((const float4*)A)[gr * 16 + quad];
        if (relu_in) {
            v.x = fmaxf(v.x, 0.f); v.y = fmaxf(v.y, 0.f);
            v.z = fmaxf(v.z, 0.f); v.w = fmaxf(v.w, 0.f);
        }
        float* dst = sA + row * SA_STRIDE + quad * 4;
        dst[0] = v.x; dst[1] = v.y; dst[2] = v.z; dst[3] = v.w;
    }
    __syncthreads();

    const int q2  = t & 7;
    const int grp = t >> 3;
    unsigned long long acc[4][4];
    #pragma unroll
    for (int r = 0; r < 4; r++)
        #pragma unroll
        for (int p = 0; p < 4; p++) acc[r][p] = 0ull;

    const float* wbase = sW + q2 * 8;
    const float* abase = sA + grp * 4 * SA_STRIDE;

    #pragma unroll 8
    for (int k = 0; k < 64; k++) {
        const float* wr = wbase + k * 64;
        unsigned long long w0 = *(const unsigned long long*)(wr + 0);
        unsigned long long w1 = *(const unsigned long long*)(wr + 2);
        unsigned long long w2 = *(const unsigned long long*)(wr + 4);
        unsigned long long w3 = *(const unsigned long long*)(wr + 6);
        #pragma unroll
        for (int r = 0; r < 4; r++) {
            unsigned long long a2 = dupf(abase[r * SA_STRIDE + k]);
            fma2(acc[r][0], a2, w0);
            fma2(acc[r][1], a2, w1);
            fma2(acc[r][2], a2, w2);
            fma2(acc[r][3], a2, w3);
        }
    }

    #pragma unroll
    for (int r = 0; r < 4; r++) {
        int gr = base + grp * 4 + r;
        if (gr >= N_NODES) continue;
        float2 f0 = unpack2(acc[r][0]), f1 = unpack2(acc[r][1]);
        float2 f2 = unpack2(acc[r][2]), f3 = unpack2(acc[r][3]);
        float4* out = (float4*)g_h + gr * 16 + q2 * 2;
        out[0] = make_float4(f0.x, f0.y, f1.x, f1.y);
        out[1] = make_float4(f2.x, f2.y, f3.x, f3.y);
    }
}

// ---------------------------------------------------------------------------
// CSR aggregation: agg[i] = h[i]*dinv[i]^2 + bias + sum_{e: col==i} h[row_e]*norm_e
// 16 threads per node (one float4 slice each); no atomics.
// ---------------------------------------------------------------------------
__global__ __launch_bounds__(256) void agg_kernel(const float* __restrict__ bias) {
    int gid = blockIdx.x * blockDim.x + threadIdx.x;
    if (gid >= N_NODES * 16) return;
    int node = gid >> 4, q = gid & 15;
    int j   = g_off[node];
    int end = g_off[node + 1];
    const float4* h4 = (const float4*)g_h;

    float4 acc = make_float4(0.f, 0.f, 0.f, 0.f);
    for (; j + 2 <= end; j += 2) {
        float2 e0 = g_edge[j], e1 = g_edge[j + 1];
        float4 v0 = h4[(__float_as_int(e0.x) << 4) + q];
        float4 v1 = h4[(__float_as_int(e1.x) << 4) + q];
        acc.x += v0.x * e0.y + v1.x * e1.y;
        acc.y += v0.y * e0.y + v1.y * e1.y;
        acc.z += v0.z * e0.y + v1.z * e1.y;
        acc.w += v0.w * e0.y + v1.w * e1.y;
    }
    if (j < end) {
        float2 e0 = g_edge[j];
        float4 v0 = h4[(__float_as_int(e0.x) << 4) + q];
        acc.x += v0.x * e0.y; acc.y += v0.y * e0.y;
        acc.z += v0.z * e0.y; acc.w += v0.w * e0.y;
    }
    float di = g_dinv[node];
    float s  = di * di;
    float4 h = h4[gid];
    float4 b = ((const float4*)bias)[q];
    acc.x += h.x * s + b.x; acc.y += h.y * s + b.y;
    acc.z += h.z * s + b.z; acc.w += h.w * s + b.w;
    ((float4*)g_agg)[gid] = acc;
}

// ---------------------------------------------------------------------------
// graph boundaries: warp-cooperative 32-ary lower_bound on sorted batch
// ---------------------------------------------------------------------------
__global__ void bounds_kernel(const void* __restrict__ batch) {
    int warp = (blockIdx.x * blockDim.x + threadIdx.x) >> 5;
    int lane = threadIdx.x & 31;
    if (warp > N_GRAPHS) return;
    int target = warp;
    int lo = 0, hi = N_NODES;               // answer in [lo, hi]
    while (hi - lo > 32) {
        long long n = hi - lo;
        int pos = lo + (int)(((long long)(lane + 1) * n) >> 5);
        bool pred = (pos < hi) && (load_bat(batch, pos) < target);
        unsigned m = __ballot_sync(0xffffffffu, pred);
        int k = __popc(m);
        int nlo = (k == 0) ? lo : (lo + (int)(((long long)k * n) >> 5) + 1);
        int nhi = lo + (int)(((long long)(k + 1) * n) >> 5);
        if (nhi > hi) nhi = hi;
        lo = nlo; hi = nhi;
    }
    int pos = lo + lane;
    bool found = (pos < hi) && (load_bat(batch, pos) >= target);
    unsigned m = __ballot_sync(0xffffffffu, found);
    int ans = m ? (lo + __ffs(m) - 1) : hi;
    if (lane == 0) g_lb[warp] = ans;
}

__global__ void pool_kernel(const void* __restrict__ batch) {
    int id = blockIdx.x * blockDim.x + threadIdx.x;
    if (id >= N_NODES * 16) return;
    int node = id >> 4, q = id & 15;
    int b = load_bat(batch, node);
    float4 v = ((const float4*)g_agg)[id];
    red_add_v4(&g_pool[b * D + q * 4], v);
}

__global__ void final_kernel(const float* __restrict__ linW,
                             const float* __restrict__ linb,
                             float* __restrict__ out) {
    int id = blockIdx.x * blockDim.x + threadIdx.x;
    if (id >= N_GRAPHS * N_CLASSES) return;
    int b = id / N_CLASSES, c = id % N_CLASSES;
    int cnt = g_lb[b + 1] - g_lb[b];
    float inv = 1.0f / fmaxf((float)cnt, 1.0f);
    float acc = linb[c];
    #pragma unroll
    for (int d = 0; d < D; d++)
        acc += (g_pool[b * D + d] * inv) * linW[d * N_CLASSES + c];
    out[id] = acc;
}

extern "C" void kernel_launch(void* const* d_in, const int* in_sizes, int n_in,
                              void* d_out, int out_size) {
    const float* x    = (const float*)d_in[0];
    const void*  ei   = d_in[1];
    const void*  bat  = d_in[2];
    const float* W1   = (const float*)d_in[3];
    const float* b1   = (const float*)d_in[4];
    const float* W2   = (const float*)d_in[5];
    const float* b2   = (const float*)d_in[6];
    const float* W3   = (const float*)d_in[7];
    const float* b3   = (const float*)d_in[8];
    const float* linW = (const float*)d_in[9];
    const float* linb = (const float*)d_in[10];
    float* out = (float*)d_out;

    void *deg_p, *pool_p, *agg_p;
    cudaGetSymbolAddress(&deg_p,  g_deg);
    cudaGetSymbolAddress(&pool_p, g_pool);
    cudaGetSymbolAddress(&agg_p,  g_agg);
    const float* agg = (const float*)agg_p;

    cudaMemsetAsync(deg_p,  0, N_NODES * sizeof(int));
    cudaMemsetAsync(pool_p, 0, N_GRAPHS * D * sizeof(float));

    detect_kernel<<<1, 256>>>((const int*)ei, (const int*)bat);
    deg_kernel<<<(N_EDGES + 255) / 256, 256>>>(ei);
    dinv_kernel<<<(N_NODES + 255) / 256, 256>>>();
    bounds_kernel<<<17, 256>>>(bat);
    scan1_kernel<<<SCAN_NB, 256>>>();
    scan2_kernel<<<1, 128>>>();
    scan3_kernel<<<SCAN_NB, 256>>>();
    fill_kernel<<<(N_EDGES + 255) / 256, 256>>>(ei);

    const int GEMM_BLOCKS = (N_NODES + 63) / 64;
    const int NODE16      = (N_NODES * 16 + 255) / 256;

    gemm_kernel<<<GEMM_BLOCKS, 128>>>(x, W1, 0);
    agg_kernel<<<NODE16, 256>>>(b1);
    gemm_kernel<<<GEMM_BLOCKS, 128>>>(agg, W2, 1);
    agg_kernel<<<NODE16, 256>>>(b2);
    gemm_kernel<<<GEMM_BLOCKS, 128>>>(agg, W3, 1);
    agg_kernel<<<NODE16, 256>>>(b3);

    pool_kernel<<<NODE16, 256>>>(bat);
    final_kernel<<<(N_GRAPHS * N_CLASSES + 255) / 256, 256>>>(linW, linb, out);
}